// round 7
// baseline (speedup 1.0000x reference)
#include <cuda_runtime.h>

#define NN 384
#define DD 128
#define TS 32
#define NT 256
#define GRID 144            // 12x12 tiles; <= 148 SMs -> all co-resident
#define SPAD 34             // k-major smem row stride (floats), 8B-aligned pairs
#define MARGIN_F 0.2f
#define MAXPOS 64

// Scratch (no allocations allowed)
__device__ float g_dot[NN * NN];
__device__ float g_r[NN];
__device__ float g_total;
__device__ float g_count;
__device__ unsigned int g_bar;
__device__ unsigned int g_ctr;

__global__ void __launch_bounds__(NT) fused_k(
    const float* __restrict__ feat,
    const int*   __restrict__ y,
    float*       __restrict__ out)
{
    const int t = threadIdx.x;
    const int b = blockIdx.x;
    const int w = t >> 5, lane = t & 31;
    const unsigned FULL = 0xFFFFFFFFu;

    __shared__ float A2[DD][SPAD];   // [k][i]
    __shared__ float B2[DD][SPAD];   // [k][j]
    __shared__ int   ys[NN];
    __shared__ float pos_d[3][MAXPOS];
    __shared__ int   wc[3][12];
    __shared__ int   wbase[3][12];
    __shared__ int   np_s[3];
    __shared__ float red_f[8];

    // ---------------- Phase 1: GEMM tile (feat @ feat^T) ----------------
    const int by = b / 12, bx = b % 12;
    const int i0 = by * TS, j0 = bx * TS;

    // stage labels (overlap with GEMM staging)
    for (int q = t; q < NN; q += NT) ys[q] = y[q];

    // stage A,B tiles transposed to k-major
#pragma unroll
    for (int r = 0; r < 4; r++) {
        const int q = r * NT + t;          // 0..1023
        const int row = q >> 5;            // 0..31
        const int k4 = (q & 31) * 4;       // k base
        const float4 av = *reinterpret_cast<const float4*>(feat + (i0 + row) * DD + k4);
        const float4 bv = *reinterpret_cast<const float4*>(feat + (j0 + row) * DD + k4);
        A2[k4 + 0][row] = av.x; A2[k4 + 1][row] = av.y;
        A2[k4 + 2][row] = av.z; A2[k4 + 3][row] = av.w;
        B2[k4 + 0][row] = bv.x; B2[k4 + 1][row] = bv.y;
        B2[k4 + 2][row] = bv.z; B2[k4 + 3][row] = bv.w;
    }
    __syncthreads();

    const int tx = t & 15, ty = t >> 4;
    float c00 = 0.f, c01 = 0.f, c10 = 0.f, c11 = 0.f;
#pragma unroll 8
    for (int k = 0; k < DD; k++) {
        const float2 a  = *reinterpret_cast<const float2*>(&A2[k][2 * ty]);
        const float2 bb = *reinterpret_cast<const float2*>(&B2[k][2 * tx]);
        c00 += a.x * bb.x; c01 += a.x * bb.y;
        c10 += a.y * bb.x; c11 += a.y * bb.y;
    }

    const int gi = i0 + 2 * ty, gj = j0 + 2 * tx;
    *reinterpret_cast<float2*>(&g_dot[gi * NN + gj])       = make_float2(c00, c01);
    *reinterpret_cast<float2*>(&g_dot[(gi + 1) * NN + gj]) = make_float2(c10, c11);
    if (bx == by && tx == ty) {
        g_r[gi]     = c00;
        g_r[gi + 1] = c11;
    }

    // ---------------- grid barrier (all 144 blocks co-resident) ----------------
    __threadfence();          // make this thread's g_dot/g_r stores visible
    __syncthreads();          // all threads fenced before arrival
    if (t == 0) {
        unsigned v = atomicAdd(&g_bar, 1u) + 1u;
        while (v < GRID) {
            __nanosleep(32);
            v = *(volatile unsigned int*)&g_bar;
        }
    }
    __syncthreads();
    __threadfence();          // acquire side

    // ---------------- Phase 2: triplet loss ----------------
    // anchors: blocks 0..95 -> 3 anchors, 96..143 -> 2 anchors
    const int ab = (b < 96) ? 3 * b : 288 + 2 * (b - 96);
    const int ac = (b < 96) ? 3 : 2;

    const int j1 = t;
    const int j2 = t + NT;                 // valid if < NN (t < 128)
    const bool has2 = (j2 < NN);
    const float rj1 = g_r[j1];
    const float rj2 = has2 ? g_r[j2] : 0.0f;

    float d21[3], d22[3];
    bool  isp1[3], isp2[3];
    unsigned pm1[3], pm2[3];

#pragma unroll
    for (int m = 0; m < 3; m++) {
        if (m < ac) {
            const int a  = ab + m;
            const int ya = ys[a];
            const float ra = g_r[a];
            const float dot1 = g_dot[a * NN + j1];
            d21[m] = fmaxf(ra + rj1 - 2.0f * dot1, 0.0f);
            isp1[m] = (ys[j1] == ya) && (j1 != a);
            pm1[m] = __ballot_sync(FULL, isp1[m]);
            float dv2 = 0.0f;
            bool p2 = false;
            if (has2) {
                const float dot2 = g_dot[a * NN + j2];
                dv2 = fmaxf(ra + rj2 - 2.0f * dot2, 0.0f);
                p2 = (ys[j2] == ya) && (j2 != a);
            }
            d22[m] = dv2;
            isp2[m] = p2;
            pm2[m] = __ballot_sync(FULL, p2);
            if (lane == 0) {
                wc[m][w] = __popc(pm1[m]);
                if (w < 4) wc[m][8 + w] = __popc(pm2[m]);
            }
        }
    }
    __syncthreads();

    if (t < ac) {
        int s = 0;
#pragma unroll
        for (int ww = 0; ww < 12; ww++) { wbase[t][ww] = s; s += wc[t][ww]; }
        np_s[t] = s;
    }
    __syncthreads();

#pragma unroll
    for (int m = 0; m < 3; m++) {
        if (m < ac) {
            if (isp1[m]) {
                const int idx = wbase[m][w] + __popc(pm1[m] & ((1u << lane) - 1u));
                pos_d[m][idx] = d21[m] + MARGIN_F;
            }
            if (isp2[m]) {
                const int idx = wbase[m][8 + w] + __popc(pm2[m] & ((1u << lane) - 1u));
                pos_d[m][idx] = d22[m] + MARGIN_F;
            }
        }
    }
    __syncthreads();

    float acc = 0.0f;
#pragma unroll
    for (int m = 0; m < 3; m++) {
        if (m < ac) {
            const int a  = ab + m;
            const int ya = ys[a];
            const int npm = np_s[m];
            if (ys[j1] != ya) {
                const float dn = d21[m];
                for (int i = 0; i < npm; i++) {
                    const float v = pos_d[m][i] - dn;
                    acc += (v > 0.0f) ? v : 0.0f;
                }
            }
            if (has2 && ys[j2] != ya) {
                const float dn = d22[m];
                for (int i = 0; i < npm; i++) {
                    const float v = pos_d[m][i] - dn;
                    acc += (v > 0.0f) ? v : 0.0f;
                }
            }
        }
    }

    // ---------------- reduce + finalize ----------------
#pragma unroll
    for (int off = 16; off > 0; off >>= 1)
        acc += __shfl_down_sync(FULL, acc, off);
    if (lane == 0) red_f[w] = acc;
    __syncthreads();
    if (w == 0) {
        float af = (lane < 8) ? red_f[lane] : 0.0f;
#pragma unroll
        for (int off = 4; off > 0; off >>= 1)
            af += __shfl_down_sync(FULL, af, off);
        if (lane == 0) {
            int cnt = 0;
            for (int m = 0; m < ac; m++)
                cnt += np_s[m] * (NN - 1 - np_s[m]);
            atomicAdd(&g_total, af);
            atomicAdd(&g_count, (float)cnt);
            __threadfence();
            const unsigned done = atomicAdd(&g_ctr, 1u);
            if (done == GRID - 1) {
                const float tot = atomicAdd(&g_total, 0.0f);
                const float cn  = atomicAdd(&g_count, 0.0f);
                out[0] = tot / cn;
                g_total = 0.0f;
                g_count = 0.0f;
                g_ctr   = 0u;
                g_bar   = 0u;
            }
        }
    }
}

extern "C" void kernel_launch(void* const* d_in, const int* in_sizes, int n_in,
                              void* d_out, int out_size) {
    const float* feat = (const float*)d_in[0];
    // d_in[1] = logits (unused by the loss)
    const int*   yv   = (const int*)d_in[2];
    float* out = (float*)d_out;

    fused_k<<<GRID, NT>>>(feat, yv, out);
}

// round 8
// speedup vs baseline: 1.1562x; 1.1562x over previous
#include <cuda_runtime.h>

#define NN 384
#define DD 128
#define MARGIN_F 0.2f
#define TSM 16
#define TSN 64
#define NT 256
#define APAD 18            // A smem row stride (even -> 8B-aligned float2)
#define BPAD 66            // B smem row stride
#define MAXPOS 64
#define NWARP_T 12

// Scratch (no allocations allowed)
__device__ float g_dot[NN * NN];
__device__ float g_r[NN];
__device__ float g_total;
__device__ float g_count;
__device__ unsigned int g_ctr;

// ---- GEMM: 16x64 tile, warp-row ownership (A reads are warp-uniform) ----
__global__ void __launch_bounds__(NT) gemm_k(const float* __restrict__ feat) {
    __shared__ float A2[DD][APAD];   // [k][i]  8.7KB
    __shared__ float B2[DD][BPAD];   // [k][j]  33.8KB

    const int t = threadIdx.x;
    const int w = t >> 5, lane = t & 31;
    const int j0 = blockIdx.x * TSN;   // 0..5
    const int i0 = blockIdx.y * TSM;   // 0..23
    const unsigned FULL = 0xFFFFFFFFu;

    // stage A: 16 rows x 32 float4 (k-major), fold in norms for bx==0
#pragma unroll
    for (int r = 0; r < 2; r++) {
        const int row = r * 8 + w;       // warp-uniform row
        const int k4 = lane;
        const float4 v = *reinterpret_cast<const float4*>(feat + (i0 + row) * DD + k4 * 4);
        A2[4 * k4 + 0][row] = v.x; A2[4 * k4 + 1][row] = v.y;
        A2[4 * k4 + 2][row] = v.z; A2[4 * k4 + 3][row] = v.w;
        if (blockIdx.x == 0) {
            float ss = v.x * v.x + v.y * v.y + v.z * v.z + v.w * v.w;
#pragma unroll
            for (int off = 16; off > 0; off >>= 1)
                ss += __shfl_down_sync(FULL, ss, off);
            if (lane == 0) g_r[i0 + row] = ss;
        }
    }
    // stage B: 64 rows x 32 float4
#pragma unroll
    for (int r = 0; r < 8; r++) {
        const int row = r * 8 + w;
        const int k4 = lane;
        const float4 v = *reinterpret_cast<const float4*>(feat + (j0 + row) * DD + k4 * 4);
        B2[4 * k4 + 0][row] = v.x; B2[4 * k4 + 1][row] = v.y;
        B2[4 * k4 + 2][row] = v.z; B2[4 * k4 + 3][row] = v.w;
    }
    __syncthreads();

    // compute: warp w -> rows {2w, 2w+1}; lane -> cols {2*lane, 2*lane+1}
    float c00 = 0.f, c01 = 0.f, c10 = 0.f, c11 = 0.f;
#pragma unroll 4
    for (int k = 0; k < DD; k++) {
        const float2 a  = *reinterpret_cast<const float2*>(&A2[k][2 * w]);     // broadcast
        const float2 bb = *reinterpret_cast<const float2*>(&B2[k][2 * lane]);  // conflict-free
        c00 += a.x * bb.x; c01 += a.x * bb.y;
        c10 += a.y * bb.x; c11 += a.y * bb.y;
    }

    const int gi = i0 + 2 * w;
    const int gj = j0 + 2 * lane;
    *reinterpret_cast<float2*>(&g_dot[gi * NN + gj])       = make_float2(c00, c01);
    *reinterpret_cast<float2*>(&g_dot[(gi + 1) * NN + gj]) = make_float2(c10, c11);
}

// ---- triplet: one anchor per block, 384 blocks x 384 threads ----
__global__ void __launch_bounds__(NN) trip_k(const int* __restrict__ y,
                                             float* __restrict__ out) {
    const int t = threadIdx.x;        // column j
    const int a = blockIdx.x;         // anchor
    const int w = t >> 5, lane = t & 31;
    const unsigned FULL = 0xFFFFFFFFu;

    __shared__ float pos_d[MAXPOS];
    __shared__ int   wc[NWARP_T];
    __shared__ int   wbase[NWARP_T];
    __shared__ int   np_sh;
    __shared__ float red_f[NWARP_T];

    const int   ya = __ldg(&y[a]);    // uniform
    const int   yj = __ldg(&y[t]);
    const float ra = g_r[a];
    const float rj = g_r[t];
    const float dot = g_dot[a * NN + t];
    const float d2 = fmaxf(ra + rj - 2.0f * dot, 0.0f);

    const bool isp = (yj == ya) && (t != a);
    const unsigned pm = __ballot_sync(FULL, isp);
    if (lane == 0) wc[w] = __popc(pm);
    __syncthreads();
    if (t == 0) {
        int s = 0;
#pragma unroll
        for (int ww = 0; ww < NWARP_T; ww++) { wbase[ww] = s; s += wc[ww]; }
        np_sh = s;
    }
    __syncthreads();
    if (isp) pos_d[wbase[w] + __popc(pm & ((1u << lane) - 1u))] = d2 + MARGIN_F;
    __syncthreads();

    const int np = np_sh;
    float acc = 0.0f;
    if (yj != ya) {
        for (int i = 0; i < np; i++) {
            const float v = pos_d[i] - d2;
            acc += (v > 0.0f) ? v : 0.0f;
        }
    }

    // block reduction + global accumulate + last-block finalize
#pragma unroll
    for (int off = 16; off > 0; off >>= 1)
        acc += __shfl_down_sync(FULL, acc, off);
    if (lane == 0) red_f[w] = acc;
    __syncthreads();
    if (w == 0) {
        float af = (lane < NWARP_T) ? red_f[lane] : 0.0f;
#pragma unroll
        for (int off = 8; off > 0; off >>= 1)
            af += __shfl_down_sync(FULL, af, off);
        if (lane == 0) {
            atomicAdd(&g_total, af);
            atomicAdd(&g_count, (float)(np * (NN - 1 - np)));
            __threadfence();
            const unsigned done = atomicAdd(&g_ctr, 1u);
            if (done == NN - 1) {
                const float tot = atomicAdd(&g_total, 0.0f);
                const float cn  = atomicAdd(&g_count, 0.0f);
                out[0] = tot / cn;
                g_total = 0.0f;
                g_count = 0.0f;
                g_ctr   = 0u;
            }
        }
    }
}

extern "C" void kernel_launch(void* const* d_in, const int* in_sizes, int n_in,
                              void* d_out, int out_size) {
    const float* feat = (const float*)d_in[0];
    // d_in[1] = logits (unused by the loss)
    const int*   yv   = (const int*)d_in[2];
    float* out = (float*)d_out;

    gemm_k<<<dim3(NN / TSN, NN / TSM), NT>>>(feat);
    trip_k<<<NN, NN>>>(yv, out);
}